// round 7
// baseline (speedup 1.0000x reference)
#include <cuda_runtime.h>
#include <cuda_fp16.h>
#include <cstdint>

#define NN 100000
#define EE 1600000
#define HF 128           // HEADS * OUT_F
#define NB_SCAN 98       // ceil(NN/1024)
#define ROWS_B 48        // rows per gemm block
#define NGEMM 2084       // ceil(NN/48)
#define NCOUNT 6250      // ceil(EE/256)

// ---------------- scratch ----------------
__device__ unsigned int g_hh[NN * 64];  // 25.6 MB : h in half2 (64 x uint per row)
__device__ float g_asrc[NN * 4];
__device__ float g_adst[NN * 4];
__device__ int   g_deg[NN];
__device__ int   g_cursor[NN];
__device__ int   g_rowstart[NN + 1];
__device__ int   g_srcs[EE + NN];
__device__ int   g_bsums[NB_SCAN];
__device__ int   g_is64;

// ---------------- packed fp32x2 helpers ----------------
__device__ __forceinline__ unsigned long long pack2(float lo, float hi) {
    unsigned long long r;
    asm("mov.b64 %0, {%1, %2};" : "=l"(r) : "f"(lo), "f"(hi));
    return r;
}
__device__ __forceinline__ void unpack2(unsigned long long v, float& lo, float& hi) {
    asm("mov.b64 {%0, %1}, %2;" : "=f"(lo), "=f"(hi) : "l"(v));
}
#define FFMA2(acc, a, b) asm("fma.rn.f32x2 %0, %1, %2, %0;" : "+l"(acc) : "l"(a), "l"(b))

// ---------------- CSR side chain ----------------
__global__ void init_kernel(const int* ei32) {
    if (blockIdx.x == 0) {
        __shared__ int nz;
        if (threadIdx.x == 0) nz = 0;
        __syncthreads();
        if (ei32[threadIdx.x * 2 + 1] != 0) atomicAdd(&nz, 1);
        __syncthreads();
        if (threadIdx.x == 0) g_is64 = (nz == 0) ? 1 : 0;
    }
    int i = blockIdx.x * blockDim.x + threadIdx.x;
    if (i < NN) g_deg[i] = 0;
}

__global__ void count_kernel(const void* __restrict__ eiv) {
    int t = blockIdx.x * 256 + threadIdx.x;
    if (t < EE) {
        int dst;
        if (g_is64) dst = (int)((const long long*)eiv)[EE + t];
        else        dst = ((const int*)eiv)[EE + t];
        atomicAdd(&g_deg[dst], 1);
    }
}

__global__ void scan_block_kernel() {
    __shared__ int sm[1024];
    int i = blockIdx.x * 1024 + threadIdx.x;
    int v = (i < NN) ? (g_deg[i] + 1) : 0;  // +1 self loop
    sm[threadIdx.x] = v;
    __syncthreads();
    for (int o = 1; o < 1024; o <<= 1) {
        int t = (threadIdx.x >= (unsigned)o) ? sm[threadIdx.x - o] : 0;
        __syncthreads();
        sm[threadIdx.x] += t;
        __syncthreads();
    }
    if (i < NN) g_rowstart[i] = sm[threadIdx.x] - v;  // exclusive within block
    if (threadIdx.x == 1023) g_bsums[blockIdx.x] = sm[1023];
}

// adds global block offset (re-scanning the 98 partials locally) + seeds cursor
__global__ void scan_add_kernel() {
    __shared__ int sp[NB_SCAN];
    if (threadIdx.x < NB_SCAN) sp[threadIdx.x] = g_bsums[threadIdx.x];
    __syncthreads();
    if (threadIdx.x == 0) {
        int acc = 0;
        for (int b = 0; b <= (int)blockIdx.x && b < NB_SCAN; b++) {
            int v = sp[b]; sp[b] = acc; acc += v;
        }
    }
    __syncthreads();
    int off = sp[blockIdx.x];
    int i = blockIdx.x * 1024 + threadIdx.x;
    if (i < NN) {
        int rs = g_rowstart[i] + off;
        g_rowstart[i] = rs;
        g_cursor[i]   = rs;
    }
    if (blockIdx.x == 0 && threadIdx.x == 0) g_rowstart[NN] = EE + NN;
}

__global__ void scatter_kernel(const void* eiv) {
    int t = blockIdx.x * blockDim.x + threadIdx.x;
    if (t >= EE + NN) return;
    int s, d;
    if (t < EE) {
        if (g_is64) {
            s = (int)((const long long*)eiv)[t];
            d = (int)((const long long*)eiv)[EE + t];
        } else {
            s = ((const int*)eiv)[t];
            d = ((const int*)eiv)[EE + t];
        }
    } else {
        s = d = t - EE;  // self loop
    }
    int p = atomicAdd(&g_cursor[d], 1);
    g_srcs[p] = s;
}

// ---------------- GEMM (+att epilogue, fp16 h store) ----------------
// 48 rows/block, 8 warps x 6 rows; lane owns cols [lane*4, lane*4+4)
// x staged DUPLICATED in smem so LDS.128 yields packed broadcast operands
__global__ __launch_bounds__(256) void gemm_kernel(
    const float* __restrict__ x, const float* __restrict__ W,
    const float* __restrict__ att_src, const float* __restrict__ att_dst) {
    __shared__ float xs[ROWS_B * HF * 2];  // 48 KB
    const int warp = threadIdx.x >> 5;
    const int lane = threadIdx.x & 31;
    const int blk_row0 = blockIdx.x * ROWS_B;

#pragma unroll
    for (int it = 0; it < 6; it++) {
        int idx = it * 256 + threadIdx.x;         // float4 index, 1536 total
        int row = idx >> 5, c4 = (idx & 31) * 4;
        float4 v = make_float4(0.f, 0.f, 0.f, 0.f);
        if (blk_row0 + row < NN) v = *(const float4*)(x + (size_t)(blk_row0 + row) * HF + c4);
        float* p = xs + (row * HF + c4) * 2;
        p[0] = v.x; p[1] = v.x; p[2] = v.y; p[3] = v.y;
        p[4] = v.z; p[5] = v.z; p[6] = v.w; p[7] = v.w;
    }
    __syncthreads();

    const float* xw = xs + warp * 6 * HF * 2;
    unsigned long long acc01[6], acc23[6];
    const unsigned long long z = pack2(0.f, 0.f);
#pragma unroll
    for (int r = 0; r < 6; r++) { acc01[r] = z; acc23[r] = z; }

#pragma unroll 4
    for (int k = 0; k < HF; k += 2) {
        float4 w0 = *(const float4*)(W + k * HF + lane * 4);
        float4 w1 = *(const float4*)(W + (k + 1) * HF + lane * 4);
        unsigned long long w0_01 = pack2(w0.x, w0.y), w0_23 = pack2(w0.z, w0.w);
        unsigned long long w1_01 = pack2(w1.x, w1.y), w1_23 = pack2(w1.z, w1.w);
#pragma unroll
        for (int r = 0; r < 6; r++) {
            ulonglong2 s = *(const ulonglong2*)(xw + (r * HF + k) * 2);
            FFMA2(acc01[r], s.x, w0_01);
            FFMA2(acc23[r], s.x, w0_23);
            FFMA2(acc01[r], s.y, w1_01);
            FFMA2(acc23[r], s.y, w1_23);
        }
    }

    const int head = lane >> 3;
    const int fo   = (lane & 7) * 4;
    float4 s4 = *(const float4*)(att_src + head * 32 + fo);
    float4 d4 = *(const float4*)(att_dst + head * 32 + fo);

#pragma unroll
    for (int r = 0; r < 6; r++) {
        int row = blk_row0 + warp * 6 + r;
        if (row >= NN) continue;
        float4 a;
        unpack2(acc01[r], a.x, a.y);
        unpack2(acc23[r], a.z, a.w);
        half2 h01 = __floats2half2_rn(a.x, a.y);
        half2 h23 = __floats2half2_rn(a.z, a.w);
        uint2 hp;
        hp.x = *(unsigned int*)&h01;
        hp.y = *(unsigned int*)&h23;
        *(uint2*)(g_hh + (size_t)row * 64 + lane * 2) = hp;
        float ps = a.x * s4.x + a.y * s4.y + a.z * s4.z + a.w * s4.w;
        float pd = a.x * d4.x + a.y * d4.y + a.z * d4.z + a.w * d4.w;
#pragma unroll
        for (int o = 1; o < 8; o <<= 1) {
            ps += __shfl_xor_sync(0xFFFFFFFFu, ps, o);
            pd += __shfl_xor_sync(0xFFFFFFFFu, pd, o);
        }
        if ((lane & 7) == 0) {
            g_asrc[row * 4 + head] = ps;
            g_adst[row * 4 + head] = pd;
        }
    }
}

// ---------------- aggregation: 4-wide software pipeline ----------------
__device__ __forceinline__ float lrelu_exp(float e) {
    e = (e > 0.f) ? e : 0.2f * e;
    return __expf(e);
}

__global__ __launch_bounds__(256) void aggregate_kernel(
    const float* __restrict__ bias, float* __restrict__ out) {
    const int warp = threadIdx.x >> 5;
    const int lane = threadIdx.x & 31;
    const int i = blockIdx.x * 8 + warp;
    if (i >= NN) return;

    const int head = lane >> 3;
    const float adst = g_adst[i * 4 + head];
    const int start = g_rowstart[i];
    const int end   = g_rowstart[i + 1];

    float4 acc = make_float4(0.f, 0.f, 0.f, 0.f);
    float ssum = 0.f;

    for (int j = start; j < end; j += 4) {
        int rem = end - j;
        // batch 4 srcs (tail duplicates s0, weight forced to 0)
        int s0 = g_srcs[j];
        int s1 = g_srcs[(rem > 1) ? j + 1 : j];
        int s2 = g_srcs[(rem > 2) ? j + 2 : j];
        int s3 = g_srcs[(rem > 3) ? j + 3 : j];
        // 4 independent logit loads + 4 independent row gathers in flight
        float a0 = g_asrc[s0 * 4 + head];
        float a1 = g_asrc[s1 * 4 + head];
        float a2 = g_asrc[s2 * 4 + head];
        float a3 = g_asrc[s3 * 4 + head];
        uint2 p0 = *(const uint2*)(g_hh + (size_t)s0 * 64 + lane * 2);
        uint2 p1 = *(const uint2*)(g_hh + (size_t)s1 * 64 + lane * 2);
        uint2 p2 = *(const uint2*)(g_hh + (size_t)s2 * 64 + lane * 2);
        uint2 p3 = *(const uint2*)(g_hh + (size_t)s3 * 64 + lane * 2);

        float w0 = lrelu_exp(a0 + adst);
        float w1 = (rem > 1) ? lrelu_exp(a1 + adst) : 0.f;
        float w2 = (rem > 2) ? lrelu_exp(a2 + adst) : 0.f;
        float w3 = (rem > 3) ? lrelu_exp(a3 + adst) : 0.f;
        ssum += (w0 + w1) + (w2 + w3);

        float2 f;
        f = __half22float2(*(const half2*)&p0.x); acc.x += w0 * f.x; acc.y += w0 * f.y;
        f = __half22float2(*(const half2*)&p0.y); acc.z += w0 * f.x; acc.w += w0 * f.y;
        f = __half22float2(*(const half2*)&p1.x); acc.x += w1 * f.x; acc.y += w1 * f.y;
        f = __half22float2(*(const half2*)&p1.y); acc.z += w1 * f.x; acc.w += w1 * f.y;
        f = __half22float2(*(const half2*)&p2.x); acc.x += w2 * f.x; acc.y += w2 * f.y;
        f = __half22float2(*(const half2*)&p2.y); acc.z += w2 * f.x; acc.w += w2 * f.y;
        f = __half22float2(*(const half2*)&p3.x); acc.x += w3 * f.x; acc.y += w3 * f.y;
        f = __half22float2(*(const half2*)&p3.y); acc.z += w3 * f.x; acc.w += w3 * f.y;
    }

    float inv = 1.f / ssum;
    float4 b = *(const float4*)(bias + lane * 4);
    float4 o;
    o.x = acc.x * inv + b.x;
    o.y = acc.y * inv + b.y;
    o.z = acc.z * inv + b.z;
    o.w = acc.w * inv + b.w;
    *(float4*)(out + (size_t)i * HF + lane * 4) = o;
}

// ---------------- launch (forked-capture overlap: CSR chain || GEMM) ----------
extern "C" void kernel_launch(void* const* d_in, const int* in_sizes, int n_in,
                              void* d_out, int out_size) {
    const float* x    = (const float*)d_in[0];
    const void*  ei   = d_in[1];
    const float* W    = (const float*)d_in[2];
    const float* asv  = (const float*)d_in[3];
    const float* adv  = (const float*)d_in[4];
    const float* bias = (const float*)d_in[5];
    float* out = (float*)d_out;

    static cudaStream_t sA = nullptr;
    static cudaEvent_t evF = nullptr, evJ = nullptr;
    if (sA == nullptr) {  // one-time host resource creation (first, un-captured call)
        cudaStreamCreateWithFlags(&sA, cudaStreamNonBlocking);
        cudaEventCreateWithFlags(&evF, cudaEventDisableTiming);
        cudaEventCreateWithFlags(&evJ, cudaEventDisableTiming);
    }

    // fork: side stream runs the CSR build while main stream runs the GEMM
    cudaEventRecord(evF, 0);
    cudaStreamWaitEvent(sA, evF, 0);

    init_kernel<<<(NN + 255) / 256, 256, 0, sA>>>((const int*)ei);
    count_kernel<<<NCOUNT, 256, 0, sA>>>(ei);
    scan_block_kernel<<<NB_SCAN, 1024, 0, sA>>>();
    scan_add_kernel<<<NB_SCAN, 1024, 0, sA>>>();
    scatter_kernel<<<(EE + NN + 255) / 256, 256, 0, sA>>>(ei);

    gemm_kernel<<<NGEMM, 256>>>(x, W, asv, adv);

    // join: aggregate needs both CSR and h
    cudaEventRecord(evJ, sA);
    cudaStreamWaitEvent(0, evJ, 0);
    aggregate_kernel<<<(NN + 7) / 8, 256>>>(bias, out);
}

// round 8
// speedup vs baseline: 1.0241x; 1.0241x over previous
#include <cuda_runtime.h>
#include <cstdint>

#define NN 100000
#define EE 1600000
#define HF 128           // HEADS * OUT_F
#define NB_SCAN 98       // ceil(NN/1024)
#define ROWS_B 48        // rows per gemm block
#define NGEMM 2084       // ceil(NN/48)
#define NCOUNT 6250      // ceil(EE/256)

// ---------------- scratch ----------------
__device__ float g_h[NN * HF];          // 51.2 MB : h = x @ W (fp32)
__device__ float g_asrc[NN * 4];
__device__ float g_adst[NN * 4];
__device__ int   g_deg[NN];
__device__ int   g_cursor[NN];
__device__ int   g_rowstart[NN + 1];
__device__ int   g_srcs[EE + NN];
__device__ unsigned long long g_lb[NB_SCAN];  // lookback: (flag<<32)|blocksum
__device__ int   g_is64;

// ---------------- packed fp32x2 helpers ----------------
__device__ __forceinline__ unsigned long long pack2(float lo, float hi) {
    unsigned long long r;
    asm("mov.b64 %0, {%1, %2};" : "=l"(r) : "f"(lo), "f"(hi));
    return r;
}
__device__ __forceinline__ void unpack2(unsigned long long v, float& lo, float& hi) {
    asm("mov.b64 {%0, %1}, %2;" : "=f"(lo), "=f"(hi) : "l"(v));
}
#define FFMA2(acc, a, b) asm("fma.rn.f32x2 %0, %1, %2, %0;" : "+l"(acc) : "l"(a), "l"(b))

// ---------------- kernel 1: dtype detect + init ----------------
__global__ void init_kernel(const int* ei32) {
    if (blockIdx.x == 0) {
        __shared__ int nz;
        if (threadIdx.x == 0) nz = 0;
        __syncthreads();
        if (ei32[threadIdx.x * 2 + 1] != 0) atomicAdd(&nz, 1);
        __syncthreads();
        if (threadIdx.x == 0) g_is64 = (nz == 0) ? 1 : 0;
        if (threadIdx.x < NB_SCAN) g_lb[threadIdx.x] = 0ULL;  // clear lookback flags
    }
    int i = blockIdx.x * blockDim.x + threadIdx.x;
    if (i < NN) g_deg[i] = 0;
}

// ---------------- kernel 2: heterogeneous GEMM + degree count ----------------
// gemm blocks (bid < NGEMM): 48 rows, 8 warps x 6 rows; lane owns cols [lane*4,+4)
//   x staged DUPLICATED in smem so LDS.128 yields packed fp32x2 broadcast operands
// count blocks (bid >= NGEMM): degree histogram (runs concurrently, complementary pipes)
__global__ __launch_bounds__(256) void gemm_count_kernel(
    const float* __restrict__ x, const float* __restrict__ W,
    const float* __restrict__ att_src, const float* __restrict__ att_dst,
    const void* __restrict__ eiv) {
    if (blockIdx.x >= NGEMM) {
        int t = (blockIdx.x - NGEMM) * 256 + threadIdx.x;
        if (t < EE) {
            int dst;
            if (g_is64) dst = (int)((const long long*)eiv)[EE + t];
            else        dst = ((const int*)eiv)[EE + t];
            atomicAdd(&g_deg[dst], 1);
        }
        return;
    }

    __shared__ float xs[ROWS_B * HF * 2];  // 48 KB duplicated broadcast layout
    const int warp = threadIdx.x >> 5;
    const int lane = threadIdx.x & 31;
    const int blk_row0 = blockIdx.x * ROWS_B;

#pragma unroll
    for (int it = 0; it < 6; it++) {
        int idx = it * 256 + threadIdx.x;         // float4 index, 1536 total
        int row = idx >> 5, c4 = (idx & 31) * 4;
        float4 v = make_float4(0.f, 0.f, 0.f, 0.f);
        if (blk_row0 + row < NN) v = *(const float4*)(x + (size_t)(blk_row0 + row) * HF + c4);
        float* p = xs + (row * HF + c4) * 2;
        p[0] = v.x; p[1] = v.x; p[2] = v.y; p[3] = v.y;
        p[4] = v.z; p[5] = v.z; p[6] = v.w; p[7] = v.w;
    }
    __syncthreads();

    const float* xw = xs + warp * 6 * HF * 2;
    unsigned long long acc01[6], acc23[6];
    const unsigned long long z = pack2(0.f, 0.f);
#pragma unroll
    for (int r = 0; r < 6; r++) { acc01[r] = z; acc23[r] = z; }

#pragma unroll 4
    for (int k = 0; k < HF; k += 2) {
        float4 w0 = *(const float4*)(W + k * HF + lane * 4);
        float4 w1 = *(const float4*)(W + (k + 1) * HF + lane * 4);
        unsigned long long w0_01 = pack2(w0.x, w0.y), w0_23 = pack2(w0.z, w0.w);
        unsigned long long w1_01 = pack2(w1.x, w1.y), w1_23 = pack2(w1.z, w1.w);
#pragma unroll
        for (int r = 0; r < 6; r++) {
            ulonglong2 s = *(const ulonglong2*)(xw + (r * HF + k) * 2);  // (xk,xk | xk1,xk1)
            FFMA2(acc01[r], s.x, w0_01);
            FFMA2(acc23[r], s.x, w0_23);
            FFMA2(acc01[r], s.y, w1_01);
            FFMA2(acc23[r], s.y, w1_23);
        }
    }

    const int head = lane >> 3;
    const int fo   = (lane & 7) * 4;
    float4 s4 = *(const float4*)(att_src + head * 32 + fo);
    float4 d4 = *(const float4*)(att_dst + head * 32 + fo);

#pragma unroll
    for (int r = 0; r < 6; r++) {
        int row = blk_row0 + warp * 6 + r;
        if (row >= NN) continue;
        float4 a;
        unpack2(acc01[r], a.x, a.y);
        unpack2(acc23[r], a.z, a.w);
        *(float4*)(g_h + (size_t)row * HF + lane * 4) = a;
        float ps = a.x * s4.x + a.y * s4.y + a.z * s4.z + a.w * s4.w;
        float pd = a.x * d4.x + a.y * d4.y + a.z * d4.z + a.w * d4.w;
#pragma unroll
        for (int o = 1; o < 8; o <<= 1) {
            ps += __shfl_xor_sync(0xFFFFFFFFu, ps, o);
            pd += __shfl_xor_sync(0xFFFFFFFFu, pd, o);
        }
        if ((lane & 7) == 0) {
            g_asrc[row * 4 + head] = ps;
            g_adst[row * 4 + head] = pd;
        }
    }
}

// ---------------- kernel 3: single-kernel scan (decoupled lookback) ----------
// 98 blocks fit in one wave (98 < 148 SMs): every block publishes its aggregate
// immediately (no waiting before publish -> progress even if serialized),
// then warp 0 spin-reads all predecessors' aggregates and reduces.
__global__ __launch_bounds__(1024) void scan_fused_kernel() {
    __shared__ int sm[1024];
    __shared__ int s_off;
    const int bid = blockIdx.x;
    const int tid = threadIdx.x;
    const int i = bid * 1024 + tid;
    int v = (i < NN) ? (g_deg[i] + 1) : 0;  // +1 self loop
    sm[tid] = v;
    __syncthreads();
    for (int o = 1; o < 1024; o <<= 1) {
        int t = (tid >= (unsigned)o) ? sm[tid - o] : 0;
        __syncthreads();
        sm[tid] += t;
        __syncthreads();
    }
    int incl = sm[tid];

    // publish this block's total (flag in bit 32)
    if (tid == 1023)
        atomicExch(&g_lb[bid], (1ULL << 32) | (unsigned long long)(unsigned)incl);

    // lookback: warp 0 sums all predecessor aggregates
    if (tid < 32) {
        int sum = 0;
        for (int j = tid; j < bid; j += 32) {
            unsigned long long p;
            do { p = *((volatile unsigned long long*)&g_lb[j]); } while (!(p >> 32));
            sum += (int)(unsigned)p;
        }
#pragma unroll
        for (int o = 16; o > 0; o >>= 1) sum += __shfl_xor_sync(0xFFFFFFFFu, sum, o);
        if (tid == 0) s_off = sum;
    }
    __syncthreads();

    if (i < NN) {
        int rs = s_off + incl - v;  // exclusive global prefix
        g_rowstart[i] = rs;
        g_cursor[i]   = rs;
    }
    if (bid == NB_SCAN - 1 && tid == 1023) g_rowstart[NN] = EE + NN;
}

// ---------------- kernel 4: scatter ----------------
__global__ void scatter_kernel(const void* eiv) {
    int t = blockIdx.x * blockDim.x + threadIdx.x;
    if (t >= EE + NN) return;
    int s, d;
    if (t < EE) {
        if (g_is64) {
            s = (int)((const long long*)eiv)[t];
            d = (int)((const long long*)eiv)[EE + t];
        } else {
            s = ((const int*)eiv)[t];
            d = ((const int*)eiv)[EE + t];
        }
    } else {
        s = d = t - EE;  // self loop
    }
    int p = atomicAdd(&g_cursor[d], 1);
    g_srcs[p] = s;
}

// ---------------- kernel 5: per-destination softmax + aggregation (fp32) -----
__global__ __launch_bounds__(256) void aggregate_kernel(
    const float* __restrict__ bias, float* __restrict__ out) {
    const int warp = threadIdx.x >> 5;
    const int lane = threadIdx.x & 31;
    const int i = blockIdx.x * 8 + warp;
    if (i >= NN) return;

    const int head = lane >> 3;
    const float adst = g_adst[i * 4 + head];
    const int start = g_rowstart[i];
    const int end   = g_rowstart[i + 1];

    float4 acc = make_float4(0.f, 0.f, 0.f, 0.f);
    float ssum = 0.f;

    int src_next = g_srcs[start];
    for (int j = start; j < end; j++) {
        int src = src_next;
        if (j + 1 < end) src_next = g_srcs[j + 1];
        float e = g_asrc[src * 4 + head] + adst;
        e = (e > 0.f) ? e : 0.2f * e;
        float w = __expf(e);
        float4 hv = *(const float4*)(g_h + (size_t)src * HF + lane * 4);
        ssum += w;
        acc.x += w * hv.x;
        acc.y += w * hv.y;
        acc.z += w * hv.z;
        acc.w += w * hv.w;
    }

    float inv = 1.f / ssum;
    float4 b = *(const float4*)(bias + lane * 4);
    float4 o;
    o.x = acc.x * inv + b.x;
    o.y = acc.y * inv + b.y;
    o.z = acc.z * inv + b.z;
    o.w = acc.w * inv + b.w;
    *(float4*)(out + (size_t)i * HF + lane * 4) = o;
}

// ---------------- launch (5 kernels, single stream) ----------------
extern "C" void kernel_launch(void* const* d_in, const int* in_sizes, int n_in,
                              void* d_out, int out_size) {
    const float* x    = (const float*)d_in[0];
    const void*  ei   = d_in[1];
    const float* W    = (const float*)d_in[2];
    const float* asv  = (const float*)d_in[3];
    const float* adv  = (const float*)d_in[4];
    const float* bias = (const float*)d_in[5];
    float* out = (float*)d_out;

    init_kernel<<<(NN + 255) / 256, 256>>>((const int*)ei);
    gemm_count_kernel<<<NGEMM + NCOUNT, 256>>>(x, W, asv, adv, ei);
    scan_fused_kernel<<<NB_SCAN, 1024>>>();
    scatter_kernel<<<(EE + NN + 255) / 256, 256>>>(ei);
    aggregate_kernel<<<(NN + 7) / 8, 256>>>(bias, out);
}

// round 10
// speedup vs baseline: 1.1645x; 1.1371x over previous
#include <cuda_runtime.h>
#include <cstdint>

#define NN 100000
#define EE 1600000
#define HF 128           // HEADS * OUT_F
#define NB_SCAN 98       // ceil(NN/1024)
#define BM 64            // rows per gemm block
#define NGEMM 1563       // ceil(NN/64)
#define NCOUNT 3125      // ceil(EE/512)

// ---------------- scratch ----------------
__device__ float  g_h[NN * HF];         // 51.2 MB : h = x @ W (fp32, tf32-accurate)
__device__ float  g_asrc[NN * 4];
__device__ float  g_adst[NN * 4];
__device__ int    g_deg[NN];
__device__ int    g_cursor[NN];
__device__ int    g_rowstart[NN + 1];
__device__ int    g_srcs[EE + NN];
__device__ unsigned long long g_lb[NB_SCAN];  // lookback: (flag<<32)|blocksum
__device__ float2 g_Wp[128 * 16 * 4];   // W packed in B-fragment order, tf32-rounded
__device__ int    g_is64;

__device__ __forceinline__ float tf32r(float x) {
    asm("cvt.rna.tf32.f32 %0, %1;" : "=f"(x) : "f"(x));
    return x;
}

// ---------------- kernel 1: dtype detect + init + W fragment pack ------------
__global__ void init_kernel(const int* ei32, const float* __restrict__ W) {
    if (blockIdx.x == 0) {
        __shared__ int nz;
        if (threadIdx.x == 0) nz = 0;
        __syncthreads();
        if (ei32[threadIdx.x * 2 + 1] != 0) atomicAdd(&nz, 1);
        __syncthreads();
        if (threadIdx.x == 0) g_is64 = (nz == 0) ? 1 : 0;
        if (threadIdx.x < NB_SCAN) g_lb[threadIdx.x] = 0ULL;
    }
    // blocks 1..32: pack W into mma B-fragment layout (8192 float2 entries)
    if (blockIdx.x >= 1 && blockIdx.x <= 32) {
        int e = (blockIdx.x - 1) * 256 + threadIdx.x;   // < 8192
        int n = e >> 6, r = e & 63, ks = r >> 2, tg = r & 3;
        float v0 = tf32r(W[(ks * 8 + tg) * HF + n]);
        float v1 = tf32r(W[(ks * 8 + tg + 4) * HF + n]);
        g_Wp[e] = make_float2(v0, v1);
    }
    int i = blockIdx.x * blockDim.x + threadIdx.x;
    if (i < NN) g_deg[i] = 0;
}

// ---------------- kernel 2: tf32 tensor GEMM (+att epilogue) + degree count --
// gemm blocks: 64 rows, 16 warps as 4m x 4n; warp = 16 rows x 32 cols (1 head)
// count blocks (bid >= NGEMM): degree histogram
__global__ __launch_bounds__(512) void gemm_count_kernel(
    const float* __restrict__ x,
    const float* __restrict__ att_src, const float* __restrict__ att_dst,
    const void* __restrict__ eiv) {
    if (blockIdx.x >= NGEMM) {
        int t = (blockIdx.x - NGEMM) * 512 + threadIdx.x;
        if (t < EE) {
            int dst;
            if (g_is64) dst = (int)((const long long*)eiv)[EE + t];
            else        dst = ((const int*)eiv)[EE + t];
            atomicAdd(&g_deg[dst], 1);
        }
        return;
    }

    __shared__ float xs[BM * 132];  // 33.8 KB, +4 pad -> conflict-free frag loads
    const int tid = threadIdx.x;
    const int blk0 = blockIdx.x * BM;

    // stage 64 rows of x, tf32-rounded
#pragma unroll
    for (int it = 0; it < 4; it++) {
        int fidx = it * 512 + tid;                // float4 index, 2048 total
        int row = fidx >> 5, c4 = (fidx & 31) * 4;
        float4 v = make_float4(0.f, 0.f, 0.f, 0.f);
        if (blk0 + row < NN) v = *(const float4*)(x + (size_t)(blk0 + row) * HF + c4);
        v.x = tf32r(v.x); v.y = tf32r(v.y); v.z = tf32r(v.z); v.w = tf32r(v.w);
        *(float4*)(xs + row * 132 + c4) = v;
    }
    __syncthreads();

    const int warp = tid >> 5, lane = tid & 31;
    const int grp = lane >> 2, tig = lane & 3;
    const int m0w = (warp >> 2) * 16;     // warp's row offset in block
    const int head = warp & 3;
    const int n0 = head * 32;

    float c[4][4];
#pragma unroll
    for (int j = 0; j < 4; j++)
#pragma unroll
        for (int q = 0; q < 4; q++) c[j][q] = 0.f;

    const float* x0 = xs + (m0w + grp) * 132;
    const float* x8 = xs + (m0w + grp + 8) * 132;

#pragma unroll
    for (int ks = 0; ks < 16; ks++) {
        int k0 = ks * 8;
        unsigned a0 = __float_as_uint(x0[k0 + tig]);
        unsigned a1 = __float_as_uint(x8[k0 + tig]);
        unsigned a2 = __float_as_uint(x0[k0 + tig + 4]);
        unsigned a3 = __float_as_uint(x8[k0 + tig + 4]);
#pragma unroll
        for (int j = 0; j < 4; j++) {
            int n = n0 + j * 8 + grp;
            float2 b = g_Wp[(n * 16 + ks) * 4 + tig];
            unsigned b0 = __float_as_uint(b.x), b1 = __float_as_uint(b.y);
            asm("mma.sync.aligned.m16n8k8.row.col.f32.tf32.tf32.f32 "
                "{%0,%1,%2,%3}, {%4,%5,%6,%7}, {%8,%9}, {%0,%1,%2,%3};"
                : "+f"(c[j][0]), "+f"(c[j][1]), "+f"(c[j][2]), "+f"(c[j][3])
                : "r"(a0), "r"(a1), "r"(a2), "r"(a3), "r"(b0), "r"(b1));
        }
    }

    // epilogue: attention logit dots (head = this warp's n-tile)
    const int row0 = blk0 + m0w + grp;
    const int row8 = row0 + 8;
    float ps0 = 0.f, pd0 = 0.f, ps1 = 0.f, pd1 = 0.f;
#pragma unroll
    for (int j = 0; j < 4; j++) {
        int col = j * 8 + tig * 2;
        float s0 = att_src[head * 32 + col], s1 = att_src[head * 32 + col + 1];
        float d0 = att_dst[head * 32 + col], d1 = att_dst[head * 32 + col + 1];
        ps0 += c[j][0] * s0 + c[j][1] * s1;
        pd0 += c[j][0] * d0 + c[j][1] * d1;
        ps1 += c[j][2] * s0 + c[j][3] * s1;
        pd1 += c[j][2] * d0 + c[j][3] * d1;
    }
#pragma unroll
    for (int o = 1; o < 4; o <<= 1) {  // reduce over the 4-lane quad (tig)
        ps0 += __shfl_xor_sync(0xFFFFFFFFu, ps0, o);
        pd0 += __shfl_xor_sync(0xFFFFFFFFu, pd0, o);
        ps1 += __shfl_xor_sync(0xFFFFFFFFu, ps1, o);
        pd1 += __shfl_xor_sync(0xFFFFFFFFu, pd1, o);
    }
    if (tig == 0 && row0 < NN) { g_asrc[row0 * 4 + head] = ps0; g_adst[row0 * 4 + head] = pd0; }
    if (tig == 0 && row8 < NN) { g_asrc[row8 * 4 + head] = ps1; g_adst[row8 * 4 + head] = pd1; }

    // store h
    if (row0 < NN) {
#pragma unroll
        for (int j = 0; j < 4; j++)
            *(float2*)(g_h + (size_t)row0 * HF + n0 + j * 8 + tig * 2) = make_float2(c[j][0], c[j][1]);
    }
    if (row8 < NN) {
#pragma unroll
        for (int j = 0; j < 4; j++)
            *(float2*)(g_h + (size_t)row8 * HF + n0 + j * 8 + tig * 2) = make_float2(c[j][2], c[j][3]);
    }
}

// ---------------- kernel 3: single-kernel scan (decoupled lookback) ----------
__global__ __launch_bounds__(1024) void scan_fused_kernel() {
    __shared__ int sm[1024];
    __shared__ int s_off;
    const int bid = blockIdx.x;
    const int tid = threadIdx.x;
    const int i = bid * 1024 + tid;
    int v = (i < NN) ? (g_deg[i] + 1) : 0;  // +1 self loop
    sm[tid] = v;
    __syncthreads();
    for (int o = 1; o < 1024; o <<= 1) {
        int t = (tid >= (unsigned)o) ? sm[tid - o] : 0;
        __syncthreads();
        sm[tid] += t;
        __syncthreads();
    }
    int incl = sm[tid];

    if (tid == 1023)
        atomicExch(&g_lb[bid], (1ULL << 32) | (unsigned long long)(unsigned)incl);

    if (tid < 32) {
        int sum = 0;
        for (int j = tid; j < bid; j += 32) {
            unsigned long long p;
            do { p = *((volatile unsigned long long*)&g_lb[j]); } while (!(p >> 32));
            sum += (int)(unsigned)p;
        }
#pragma unroll
        for (int o = 16; o > 0; o >>= 1) sum += __shfl_xor_sync(0xFFFFFFFFu, sum, o);
        if (tid == 0) s_off = sum;
    }
    __syncthreads();

    if (i < NN) {
        int rs = s_off + incl - v;
        g_rowstart[i] = rs;
        g_cursor[i]   = rs;
    }
    if (bid == NB_SCAN - 1 && tid == 1023) g_rowstart[NN] = EE + NN;
}

// ---------------- kernel 4: scatter ----------------
__global__ void scatter_kernel(const void* eiv) {
    int t = blockIdx.x * blockDim.x + threadIdx.x;
    if (t >= EE + NN) return;
    int s, d;
    if (t < EE) {
        if (g_is64) {
            s = (int)((const long long*)eiv)[t];
            d = (int)((const long long*)eiv)[EE + t];
        } else {
            s = ((const int*)eiv)[t];
            d = ((const int*)eiv)[EE + t];
        }
    } else {
        s = d = t - EE;  // self loop
    }
    int p = atomicAdd(&g_cursor[d], 1);
    g_srcs[p] = s;
}

// ---------------- kernel 5: per-destination softmax + aggregation (fp32) -----
__global__ __launch_bounds__(256) void aggregate_kernel(
    const float* __restrict__ bias, float* __restrict__ out) {
    const int warp = threadIdx.x >> 5;
    const int lane = threadIdx.x & 31;
    const int i = blockIdx.x * 8 + warp;
    if (i >= NN) return;

    const int head = lane >> 3;
    const float adst = g_adst[i * 4 + head];
    const int start = g_rowstart[i];
    const int end   = g_rowstart[i + 1];

    float4 acc = make_float4(0.f, 0.f, 0.f, 0.f);
    float ssum = 0.f;

    int src_next = g_srcs[start];
    for (int j = start; j < end; j++) {
        int src = src_next;
        if (j + 1 < end) src_next = g_srcs[j + 1];
        float e = g_asrc[src * 4 + head] + adst;
        e = (e > 0.f) ? e : 0.2f * e;
        float w = __expf(e);
        float4 hv = *(const float4*)(g_h + (size_t)src * HF + lane * 4);
        ssum += w;
        acc.x += w * hv.x;
        acc.y += w * hv.y;
        acc.z += w * hv.z;
        acc.w += w * hv.w;
    }

    float inv = 1.f / ssum;
    float4 b = *(const float4*)(bias + lane * 4);
    float4 o;
    o.x = acc.x * inv + b.x;
    o.y = acc.y * inv + b.y;
    o.z = acc.z * inv + b.z;
    o.w = acc.w * inv + b.w;
    *(float4*)(out + (size_t)i * HF + lane * 4) = o;
}

// ---------------- launch (5 kernels, single stream) ----------------
extern "C" void kernel_launch(void* const* d_in, const int* in_sizes, int n_in,
                              void* d_out, int out_size) {
    const float* x    = (const float*)d_in[0];
    const void*  ei   = d_in[1];
    const float* W    = (const float*)d_in[2];
    const float* asv  = (const float*)d_in[3];
    const float* adv  = (const float*)d_in[4];
    const float* bias = (const float*)d_in[5];
    float* out = (float*)d_out;

    init_kernel<<<(NN + 255) / 256, 256>>>((const int*)ei, W);
    gemm_count_kernel<<<NGEMM + NCOUNT, 512>>>(x, asv, adv, ei);
    scan_fused_kernel<<<NB_SCAN, 1024>>>();
    scatter_kernel<<<(EE + NN + 255) / 256, 256>>>(ei);
    aggregate_kernel<<<(NN + 7) / 8, 256>>>(bias, out);
}

// round 11
// speedup vs baseline: 1.1776x; 1.0112x over previous
#include <cuda_runtime.h>
#include <cuda_fp16.h>
#include <cstdint>

#define NN 100000
#define EE 1600000
#define HF 128           // HEADS * OUT_F
#define NB_SCAN 98       // ceil(NN/1024)
#define BM 64            // rows per gemm block
#define NGEMM 1563       // ceil(NN/64)
#define NCOUNT 3125      // ceil(EE/512)

// ---------------- scratch ----------------
__device__ unsigned int g_hh[NN * 64]; // 25.6 MB : h in half2 (64 x uint per row)
__device__ float  g_asrc[NN * 4];
__device__ float  g_adst[NN * 4];
__device__ int    g_deg[NN];
__device__ int    g_cursor[NN];
__device__ int    g_rowstart[NN + 1];
__device__ int    g_srcs[EE + NN];
__device__ unsigned long long g_lb[NB_SCAN];  // lookback: (flag<<32)|blocksum
__device__ float2 g_Wp[128 * 16 * 4];   // W packed in B-fragment order, tf32-rounded
__device__ int    g_is64;

__device__ __forceinline__ float tf32r(float x) {
    asm("cvt.rna.tf32.f32 %0, %1;" : "=f"(x) : "f"(x));
    return x;
}

// ---------------- kernel 1: dtype detect + init + W fragment pack ------------
__global__ void init_kernel(const int* ei32, const float* __restrict__ W) {
    if (blockIdx.x == 0) {
        __shared__ int nz;
        if (threadIdx.x == 0) nz = 0;
        __syncthreads();
        if (ei32[threadIdx.x * 2 + 1] != 0) atomicAdd(&nz, 1);
        __syncthreads();
        if (threadIdx.x == 0) g_is64 = (nz == 0) ? 1 : 0;
        if (threadIdx.x < NB_SCAN) g_lb[threadIdx.x] = 0ULL;
    }
    // blocks 1..32: pack W into mma B-fragment layout (8192 float2 entries)
    if (blockIdx.x >= 1 && blockIdx.x <= 32) {
        int e = (blockIdx.x - 1) * 256 + threadIdx.x;   // < 8192
        int n = e >> 6, r = e & 63, ks = r >> 2, tg = r & 3;
        float v0 = tf32r(W[(ks * 8 + tg) * HF + n]);
        float v1 = tf32r(W[(ks * 8 + tg + 4) * HF + n]);
        g_Wp[e] = make_float2(v0, v1);
    }
    int i = blockIdx.x * blockDim.x + threadIdx.x;
    if (i < NN) g_deg[i] = 0;
}

// ---------------- kernel 2: tf32 tensor GEMM (+att epilogue) + degree count --
// gemm blocks: 64 rows, 16 warps as 4m x 4n; warp = 16 rows x 32 cols (1 head)
// count blocks (bid >= NGEMM): degree histogram
__global__ __launch_bounds__(512) void gemm_count_kernel(
    const float* __restrict__ x,
    const float* __restrict__ att_src, const float* __restrict__ att_dst,
    const void* __restrict__ eiv) {
    if (blockIdx.x >= NGEMM) {
        int t = (blockIdx.x - NGEMM) * 512 + threadIdx.x;
        if (t < EE) {
            int dst;
            if (g_is64) dst = (int)((const long long*)eiv)[EE + t];
            else        dst = ((const int*)eiv)[EE + t];
            atomicAdd(&g_deg[dst], 1);
        }
        return;
    }

    __shared__ float xs[BM * 132];  // 33.8 KB, +4 pad -> conflict-free frag loads
    const int tid = threadIdx.x;
    const int blk0 = blockIdx.x * BM;

    // stage 64 rows of x, tf32-rounded
#pragma unroll
    for (int it = 0; it < 4; it++) {
        int fidx = it * 512 + tid;                // float4 index, 2048 total
        int row = fidx >> 5, c4 = (fidx & 31) * 4;
        float4 v = make_float4(0.f, 0.f, 0.f, 0.f);
        if (blk0 + row < NN) v = *(const float4*)(x + (size_t)(blk0 + row) * HF + c4);
        v.x = tf32r(v.x); v.y = tf32r(v.y); v.z = tf32r(v.z); v.w = tf32r(v.w);
        *(float4*)(xs + row * 132 + c4) = v;
    }
    __syncthreads();

    const int warp = tid >> 5, lane = tid & 31;
    const int grp = lane >> 2, tig = lane & 3;
    const int m0w = (warp >> 2) * 16;     // warp's row offset in block
    const int head = warp & 3;
    const int n0 = head * 32;

    float c[4][4];
#pragma unroll
    for (int j = 0; j < 4; j++)
#pragma unroll
        for (int q = 0; q < 4; q++) c[j][q] = 0.f;

    const float* x0 = xs + (m0w + grp) * 132;
    const float* x8 = xs + (m0w + grp + 8) * 132;

#pragma unroll
    for (int ks = 0; ks < 16; ks++) {
        int k0 = ks * 8;
        unsigned a0 = __float_as_uint(x0[k0 + tig]);
        unsigned a1 = __float_as_uint(x8[k0 + tig]);
        unsigned a2 = __float_as_uint(x0[k0 + tig + 4]);
        unsigned a3 = __float_as_uint(x8[k0 + tig + 4]);
#pragma unroll
        for (int j = 0; j < 4; j++) {
            int n = n0 + j * 8 + grp;
            float2 b = g_Wp[(n * 16 + ks) * 4 + tig];
            unsigned b0 = __float_as_uint(b.x), b1 = __float_as_uint(b.y);
            asm("mma.sync.aligned.m16n8k8.row.col.f32.tf32.tf32.f32 "
                "{%0,%1,%2,%3}, {%4,%5,%6,%7}, {%8,%9}, {%0,%1,%2,%3};"
                : "+f"(c[j][0]), "+f"(c[j][1]), "+f"(c[j][2]), "+f"(c[j][3])
                : "r"(a0), "r"(a1), "r"(a2), "r"(a3), "r"(b0), "r"(b1));
        }
    }

    // epilogue: attention logit dots (head = this warp's n-tile)
    const int row0 = blk0 + m0w + grp;
    const int row8 = row0 + 8;
    float ps0 = 0.f, pd0 = 0.f, ps1 = 0.f, pd1 = 0.f;
#pragma unroll
    for (int j = 0; j < 4; j++) {
        int col = j * 8 + tig * 2;
        float s0 = att_src[head * 32 + col], s1 = att_src[head * 32 + col + 1];
        float d0 = att_dst[head * 32 + col], d1 = att_dst[head * 32 + col + 1];
        ps0 += c[j][0] * s0 + c[j][1] * s1;
        pd0 += c[j][0] * d0 + c[j][1] * d1;
        ps1 += c[j][2] * s0 + c[j][3] * s1;
        pd1 += c[j][2] * d0 + c[j][3] * d1;
    }
#pragma unroll
    for (int o = 1; o < 4; o <<= 1) {  // reduce over the 4-lane quad (tig)
        ps0 += __shfl_xor_sync(0xFFFFFFFFu, ps0, o);
        pd0 += __shfl_xor_sync(0xFFFFFFFFu, pd0, o);
        ps1 += __shfl_xor_sync(0xFFFFFFFFu, ps1, o);
        pd1 += __shfl_xor_sync(0xFFFFFFFFu, pd1, o);
    }
    if (tig == 0 && row0 < NN) { g_asrc[row0 * 4 + head] = ps0; g_adst[row0 * 4 + head] = pd0; }
    if (tig == 0 && row8 < NN) { g_asrc[row8 * 4 + head] = ps1; g_adst[row8 * 4 + head] = pd1; }

    // store h as fp16 pairs (message payload)
    if (row0 < NN) {
#pragma unroll
        for (int j = 0; j < 4; j++) {
            half2 hp = __floats2half2_rn(c[j][0], c[j][1]);
            g_hh[(size_t)row0 * 64 + (n0 + j * 8 + tig * 2) / 2] = *(unsigned int*)&hp;
        }
    }
    if (row8 < NN) {
#pragma unroll
        for (int j = 0; j < 4; j++) {
            half2 hp = __floats2half2_rn(c[j][2], c[j][3]);
            g_hh[(size_t)row8 * 64 + (n0 + j * 8 + tig * 2) / 2] = *(unsigned int*)&hp;
        }
    }
}

// ---------------- kernel 3: single-kernel scan (decoupled lookback) ----------
__global__ __launch_bounds__(1024) void scan_fused_kernel() {
    __shared__ int sm[1024];
    __shared__ int s_off;
    const int bid = blockIdx.x;
    const int tid = threadIdx.x;
    const int i = bid * 1024 + tid;
    int v = (i < NN) ? (g_deg[i] + 1) : 0;  // +1 self loop
    sm[tid] = v;
    __syncthreads();
    for (int o = 1; o < 1024; o <<= 1) {
        int t = (tid >= (unsigned)o) ? sm[tid - o] : 0;
        __syncthreads();
        sm[tid] += t;
        __syncthreads();
    }
    int incl = sm[tid];

    if (tid == 1023)
        atomicExch(&g_lb[bid], (1ULL << 32) | (unsigned long long)(unsigned)incl);

    if (tid < 32) {
        int sum = 0;
        for (int j = tid; j < bid; j += 32) {
            unsigned long long p;
            do { p = *((volatile unsigned long long*)&g_lb[j]); } while (!(p >> 32));
            sum += (int)(unsigned)p;
        }
#pragma unroll
        for (int o = 16; o > 0; o >>= 1) sum += __shfl_xor_sync(0xFFFFFFFFu, sum, o);
        if (tid == 0) s_off = sum;
    }
    __syncthreads();

    if (i < NN) {
        int rs = s_off + incl - v;
        g_rowstart[i] = rs;
        g_cursor[i]   = rs;
    }
    if (bid == NB_SCAN - 1 && tid == 1023) g_rowstart[NN] = EE + NN;
}

// ---------------- kernel 4: scatter ----------------
__global__ void scatter_kernel(const void* eiv) {
    int t = blockIdx.x * blockDim.x + threadIdx.x;
    if (t >= EE + NN) return;
    int s, d;
    if (t < EE) {
        if (g_is64) {
            s = (int)((const long long*)eiv)[t];
            d = (int)((const long long*)eiv)[EE + t];
        } else {
            s = ((const int*)eiv)[t];
            d = ((const int*)eiv)[EE + t];
        }
    } else {
        s = d = t - EE;  // self loop
    }
    int p = atomicAdd(&g_cursor[d], 1);
    g_srcs[p] = s;
}

// ---------------- kernel 5: softmax + aggregation (fp16 gather, fp32 math) ---
__global__ __launch_bounds__(256) void aggregate_kernel(
    const float* __restrict__ bias, float* __restrict__ out) {
    const int warp = threadIdx.x >> 5;
    const int lane = threadIdx.x & 31;
    const int i = blockIdx.x * 8 + warp;
    if (i >= NN) return;

    const int head = lane >> 3;
    const float adst = g_adst[i * 4 + head];
    const int start = g_rowstart[i];
    const int end   = g_rowstart[i + 1];

    float4 acc = make_float4(0.f, 0.f, 0.f, 0.f);
    float ssum = 0.f;

    int src_next = g_srcs[start];
    for (int j = start; j < end; j++) {
        int src = src_next;
        if (j + 1 < end) src_next = g_srcs[j + 1];
        float e = g_asrc[src * 4 + head] + adst;
        e = (e > 0.f) ? e : 0.2f * e;
        float w = __expf(e);
        uint2 hp = *(const uint2*)(g_hh + (size_t)src * 64 + lane * 2);
        float2 f01 = __half22float2(*(const half2*)&hp.x);
        float2 f23 = __half22float2(*(const half2*)&hp.y);
        ssum += w;
        acc.x += w * f01.x;
        acc.y += w * f01.y;
        acc.z += w * f23.x;
        acc.w += w * f23.y;
    }

    float inv = 1.f / ssum;
    float4 b = *(const float4*)(bias + lane * 4);
    float4 o;
    o.x = acc.x * inv + b.x;
    o.y = acc.y * inv + b.y;
    o.z = acc.z * inv + b.z;
    o.w = acc.w * inv + b.w;
    *(float4*)(out + (size_t)i * HF + lane * 4) = o;
}

// ---------------- launch (5 kernels, single stream) ----------------
extern "C" void kernel_launch(void* const* d_in, const int* in_sizes, int n_in,
                              void* d_out, int out_size) {
    const float* x    = (const float*)d_in[0];
    const void*  ei   = d_in[1];
    const float* W    = (const float*)d_in[2];
    const float* asv  = (const float*)d_in[3];
    const float* adv  = (const float*)d_in[4];
    const float* bias = (const float*)d_in[5];
    float* out = (float*)d_out;

    init_kernel<<<(NN + 255) / 256, 256>>>((const int*)ei, W);
    gemm_count_kernel<<<NGEMM + NCOUNT, 512>>>(x, asv, adv, ei);
    scan_fused_kernel<<<NB_SCAN, 1024>>>();
    scatter_kernel<<<(EE + NN + 255) / 256, 256>>>(ei);
    aggregate_kernel<<<(NN + 7) / 8, 256>>>(bias, out);
}

// round 12
// speedup vs baseline: 1.3417x; 1.1394x over previous
#include <cuda_runtime.h>
#include <cuda_fp16.h>
#include <cstdint>

#define NN 100000
#define EE 1600000
#define HF 128           // HEADS * OUT_F
#define NB_SCAN 98       // ceil(NN/1024)
#define BM 64            // rows per gemm block
#define NGEMM 1563       // ceil(NN/64)
#define NSCAT 3321       // ceil((EE+NN)/512)

// ---------------- scratch (statics are zero-initialized at load) -------------
__device__ unsigned int g_hh[NN * 64]; // 25.6 MB : h in half2 (64 x uint per row)
__device__ float  g_asrc[NN * 4];
__device__ float  g_adst[NN * 4];
__device__ int    g_deg[NN];           // zeroed initially; scan re-zeroes after use
__device__ int    g_cursor[NN];
__device__ int    g_rowstart[NN + 1];
__device__ int    g_srcs[EE + NN];
__device__ unsigned long long g_lb[NB_SCAN];  // lookback: (flag<<32)|blocksum
__device__ float2 g_Wp[128 * 16 * 4];  // W packed in B-fragment order, tf32-rounded
__device__ int    g_is64;

__device__ __forceinline__ float tf32r(float x) {
    asm("cvt.rna.tf32.f32 %0, %1;" : "=f"(x) : "f"(x));
    return x;
}

// ---------------- kernel 1: dtype detect (1 block) ----------------
__global__ void detect_kernel(const int* ei32) {
    __shared__ int nz;
    if (threadIdx.x == 0) nz = 0;
    __syncthreads();
    if (ei32[threadIdx.x * 2 + 1] != 0) atomicAdd(&nz, 1);  // odd words zero => int64
    __syncthreads();
    if (threadIdx.x == 0) g_is64 = (nz == 0) ? 1 : 0;
}

// ---------------- kernel 2: degree count (+ lb clear + W fragment pack) ------
__global__ __launch_bounds__(512) void count_kernel(
    const void* __restrict__ eiv, const float* __restrict__ W) {
    const int bid = blockIdx.x, tid = threadIdx.x;
    if (bid == 0 && tid < NB_SCAN) g_lb[tid] = 0ULL;
    if (bid >= 1 && bid <= 16) {  // pack W into mma B-fragment layout (8192 float2)
        int e = (bid - 1) * 512 + tid;
        int n = e >> 6, r = e & 63, ks = r >> 2, tg = r & 3;
        float v0 = tf32r(W[(ks * 8 + tg) * HF + n]);
        float v1 = tf32r(W[(ks * 8 + tg + 4) * HF + n]);
        g_Wp[e] = make_float2(v0, v1);
    }
    int t = bid * 512 + tid;
    if (t < EE) {
        int dst;
        if (g_is64) dst = (int)((const long long*)eiv)[EE + t];
        else        dst = ((const int*)eiv)[EE + t];
        atomicAdd(&g_deg[dst], 1);
    }
}

// ---------------- kernel 3: single-kernel scan (decoupled lookback) ----------
// also resets g_deg to 0 so the next graph replay's count starts clean
__global__ __launch_bounds__(1024) void scan_fused_kernel() {
    __shared__ int sm[1024];
    __shared__ int s_off;
    const int bid = blockIdx.x;
    const int tid = threadIdx.x;
    const int i = bid * 1024 + tid;
    int v = 0;
    if (i < NN) { v = g_deg[i] + 1; g_deg[i] = 0; }  // +1 self loop; reset for replay
    sm[tid] = v;
    __syncthreads();
    for (int o = 1; o < 1024; o <<= 1) {
        int t = (tid >= (unsigned)o) ? sm[tid - o] : 0;
        __syncthreads();
        sm[tid] += t;
        __syncthreads();
    }
    int incl = sm[tid];

    if (tid == 1023)
        atomicExch(&g_lb[bid], (1ULL << 32) | (unsigned long long)(unsigned)incl);

    if (tid < 32) {
        int sum = 0;
        for (int j = tid; j < bid; j += 32) {
            unsigned long long p;
            do { p = *((volatile unsigned long long*)&g_lb[j]); } while (!(p >> 32));
            sum += (int)(unsigned)p;
        }
#pragma unroll
        for (int o = 16; o > 0; o >>= 1) sum += __shfl_xor_sync(0xFFFFFFFFu, sum, o);
        if (tid == 0) s_off = sum;
    }
    __syncthreads();

    if (i < NN) {
        int rs = s_off + incl - v;
        g_rowstart[i] = rs;
        g_cursor[i]   = rs;
    }
    if (bid == NB_SCAN - 1 && tid == 1023) g_rowstart[NN] = EE + NN;
}

// ---------------- kernel 4: tf32 tensor GEMM + CSR scatter (heterogeneous) ---
// gemm blocks: 64 rows, 16 warps as 4m x 4n; warp = 16 rows x 32 cols (1 head)
// scatter blocks (bid >= NGEMM): place edge sources into CSR slots (L2-atomic-
// bound, hides under the tensor-pipe-bound gemm blocks)
__global__ __launch_bounds__(512) void gemm_scatter_kernel(
    const float* __restrict__ x,
    const float* __restrict__ att_src, const float* __restrict__ att_dst,
    const void* __restrict__ eiv) {
    if (blockIdx.x >= NGEMM) {
        int t = (blockIdx.x - NGEMM) * 512 + threadIdx.x;
        if (t >= EE + NN) return;
        int s, d;
        if (t < EE) {
            if (g_is64) {
                s = (int)((const long long*)eiv)[t];
                d = (int)((const long long*)eiv)[EE + t];
            } else {
                s = ((const int*)eiv)[t];
                d = ((const int*)eiv)[EE + t];
            }
        } else {
            s = d = t - EE;  // self loop
        }
        int p = atomicAdd(&g_cursor[d], 1);
        g_srcs[p] = s;
        return;
    }

    __shared__ float xs[BM * 132];  // 33.8 KB, +4 pad -> conflict-free frag loads
    const int tid = threadIdx.x;
    const int blk0 = blockIdx.x * BM;

#pragma unroll
    for (int it = 0; it < 4; it++) {
        int fidx = it * 512 + tid;                // float4 index, 2048 total
        int row = fidx >> 5, c4 = (fidx & 31) * 4;
        float4 v = make_float4(0.f, 0.f, 0.f, 0.f);
        if (blk0 + row < NN) v = *(const float4*)(x + (size_t)(blk0 + row) * HF + c4);
        v.x = tf32r(v.x); v.y = tf32r(v.y); v.z = tf32r(v.z); v.w = tf32r(v.w);
        *(float4*)(xs + row * 132 + c4) = v;
    }
    __syncthreads();

    const int warp = tid >> 5, lane = tid & 31;
    const int grp = lane >> 2, tig = lane & 3;
    const int m0w = (warp >> 2) * 16;
    const int head = warp & 3;
    const int n0 = head * 32;

    float c[4][4];
#pragma unroll
    for (int j = 0; j < 4; j++)
#pragma unroll
        for (int q = 0; q < 4; q++) c[j][q] = 0.f;

    const float* x0 = xs + (m0w + grp) * 132;
    const float* x8 = xs + (m0w + grp + 8) * 132;

#pragma unroll
    for (int ks = 0; ks < 16; ks++) {
        int k0 = ks * 8;
        unsigned a0 = __float_as_uint(x0[k0 + tig]);
        unsigned a1 = __float_as_uint(x8[k0 + tig]);
        unsigned a2 = __float_as_uint(x0[k0 + tig + 4]);
        unsigned a3 = __float_as_uint(x8[k0 + tig + 4]);
#pragma unroll
        for (int j = 0; j < 4; j++) {
            int n = n0 + j * 8 + grp;
            float2 b = g_Wp[(n * 16 + ks) * 4 + tig];
            unsigned b0 = __float_as_uint(b.x), b1 = __float_as_uint(b.y);
            asm("mma.sync.aligned.m16n8k8.row.col.f32.tf32.tf32.f32 "
                "{%0,%1,%2,%3}, {%4,%5,%6,%7}, {%8,%9}, {%0,%1,%2,%3};"
                : "+f"(c[j][0]), "+f"(c[j][1]), "+f"(c[j][2]), "+f"(c[j][3])
                : "r"(a0), "r"(a1), "r"(a2), "r"(a3), "r"(b0), "r"(b1));
        }
    }

    const int row0 = blk0 + m0w + grp;
    const int row8 = row0 + 8;
    float ps0 = 0.f, pd0 = 0.f, ps1 = 0.f, pd1 = 0.f;
#pragma unroll
    for (int j = 0; j < 4; j++) {
        int col = j * 8 + tig * 2;
        float s0 = att_src[head * 32 + col], s1 = att_src[head * 32 + col + 1];
        float d0 = att_dst[head * 32 + col], d1 = att_dst[head * 32 + col + 1];
        ps0 += c[j][0] * s0 + c[j][1] * s1;
        pd0 += c[j][0] * d0 + c[j][1] * d1;
        ps1 += c[j][2] * s0 + c[j][3] * s1;
        pd1 += c[j][2] * d0 + c[j][3] * d1;
    }
#pragma unroll
    for (int o = 1; o < 4; o <<= 1) {
        ps0 += __shfl_xor_sync(0xFFFFFFFFu, ps0, o);
        pd0 += __shfl_xor_sync(0xFFFFFFFFu, pd0, o);
        ps1 += __shfl_xor_sync(0xFFFFFFFFu, ps1, o);
        pd1 += __shfl_xor_sync(0xFFFFFFFFu, pd1, o);
    }
    if (tig == 0 && row0 < NN) { g_asrc[row0 * 4 + head] = ps0; g_adst[row0 * 4 + head] = pd0; }
    if (tig == 0 && row8 < NN) { g_asrc[row8 * 4 + head] = ps1; g_adst[row8 * 4 + head] = pd1; }

    if (row0 < NN) {
#pragma unroll
        for (int j = 0; j < 4; j++) {
            half2 hp = __floats2half2_rn(c[j][0], c[j][1]);
            g_hh[(size_t)row0 * 64 + (n0 + j * 8 + tig * 2) / 2] = *(unsigned int*)&hp;
        }
    }
    if (row8 < NN) {
#pragma unroll
        for (int j = 0; j < 4; j++) {
            half2 hp = __floats2half2_rn(c[j][2], c[j][3]);
            g_hh[(size_t)row8 * 64 + (n0 + j * 8 + tig * 2) / 2] = *(unsigned int*)&hp;
        }
    }
}

// ---------------- kernel 5: softmax + aggregation, 2 nodes per warp ----------
// 16-lane group per node; lane owns 8 consecutive features (uint4 = 8 halves).
// One warp issue stream serves TWO edge streams -> ~2x issue efficiency.
__global__ __launch_bounds__(256) void aggregate_kernel(
    const float* __restrict__ bias, float* __restrict__ out) {
    const int grp = threadIdx.x >> 4;       // 16 groups per block
    const int l   = threadIdx.x & 15;
    const int i = blockIdx.x * 16 + grp;
    if (i >= NN) return;

    const int head = l >> 2;                // 4 lanes per head
    const float adst = g_adst[i * 4 + head];
    const int start = g_rowstart[i];
    const int end   = g_rowstart[i + 1];

    float acc[8];
#pragma unroll
    for (int q = 0; q < 8; q++) acc[q] = 0.f;
    float ssum = 0.f;

    int src_next = g_srcs[start];           // segment non-empty (self loop)
    for (int j = start; j < end; j++) {
        int src = src_next;
        if (j + 1 < end) src_next = g_srcs[j + 1];
        float e = g_asrc[src * 4 + head] + adst;
        e = (e > 0.f) ? e : 0.2f * e;
        float w = __expf(e);
        uint4 hp = *(const uint4*)(g_hh + (size_t)src * 64 + l * 4);  // 8 halves
        float2 f0 = __half22float2(*(const half2*)&hp.x);
        float2 f1 = __half22float2(*(const half2*)&hp.y);
        float2 f2 = __half22float2(*(const half2*)&hp.z);
        float2 f3 = __half22float2(*(const half2*)&hp.w);
        ssum += w;
        acc[0] += w * f0.x; acc[1] += w * f0.y;
        acc[2] += w * f1.x; acc[3] += w * f1.y;
        acc[4] += w * f2.x; acc[5] += w * f2.y;
        acc[6] += w * f3.x; acc[7] += w * f3.y;
    }

    float inv = 1.f / ssum;
    float4 b0 = *(const float4*)(bias + l * 8);
    float4 b1 = *(const float4*)(bias + l * 8 + 4);
    float4 o0, o1;
    o0.x = acc[0] * inv + b0.x; o0.y = acc[1] * inv + b0.y;
    o0.z = acc[2] * inv + b0.z; o0.w = acc[3] * inv + b0.w;
    o1.x = acc[4] * inv + b1.x; o1.y = acc[5] * inv + b1.y;
    o1.z = acc[6] * inv + b1.z; o1.w = acc[7] * inv + b1.w;
    *(float4*)(out + (size_t)i * HF + l * 8)     = o0;
    *(float4*)(out + (size_t)i * HF + l * 8 + 4) = o1;
}

// ---------------- launch ----------------
extern "C" void kernel_launch(void* const* d_in, const int* in_sizes, int n_in,
                              void* d_out, int out_size) {
    const float* x    = (const float*)d_in[0];
    const void*  ei   = d_in[1];
    const float* W    = (const float*)d_in[2];
    const float* asv  = (const float*)d_in[3];
    const float* adv  = (const float*)d_in[4];
    const float* bias = (const float*)d_in[5];
    float* out = (float*)d_out;

    detect_kernel<<<1, 256>>>((const int*)ei);
    count_kernel<<<3125, 512>>>(ei, W);
    scan_fused_kernel<<<NB_SCAN, 1024>>>();
    gemm_scatter_kernel<<<NGEMM + NSCAT, 512>>>(x, asv, adv, ei);
    aggregate_kernel<<<(NN + 15) / 16, 256>>>(bias, out);
}

// round 13
// speedup vs baseline: 1.5337x; 1.1431x over previous
#include <cuda_runtime.h>
#include <cuda_fp16.h>
#include <cstdint>

#define NN 100000
#define EE 1600000
#define HF 128           // HEADS * OUT_F
#define NB_SCAN 98       // ceil(NN/1024)
#define BM 64            // rows per gemm block
#define NGEMM 1563       // ceil(NN/64) total gemm blocks
#define NG1 500          // gemm blocks in launch A (rest in launch B)
#define NG2 (NGEMM - NG1)
#define NCOUNT 6250      // ceil(EE/256)
#define NSCAT 6641       // ceil((EE+NN)/256)

// ---------------- scratch (statics zero-initialized at load) -----------------
__device__ unsigned int g_hh[NN * 64]; // 25.6 MB : h in half2 (64 x uint per row)
__device__ float  g_asrc[NN * 4];
__device__ float  g_adst[NN * 4];
__device__ int    g_deg[NN];           // scan re-zeroes after use (replay-safe)
__device__ int    g_cursor[NN];
__device__ int    g_rowstart[NN + 1];
__device__ int    g_srcs[EE + NN];
__device__ unsigned long long g_lb[NB_SCAN];  // lookback: (flag<<32)|blocksum
__device__ float2 g_Wp[128 * 16 * 4];  // W in B-fragment order, tf32-rounded
__device__ int    g_is64;

__device__ __forceinline__ float tf32r(float x) {
    asm("cvt.rna.tf32.f32 %0, %1;" : "=f"(x) : "f"(x));
    return x;
}

// ---------------- kernel 1: dtype detect + lb clear + W fragment pack --------
__global__ __launch_bounds__(256) void detect_pack_kernel(
    const int* ei32, const float* __restrict__ W) {
    const int bid = blockIdx.x, tid = threadIdx.x;
    if (bid == 0) {
        __shared__ int nz;
        if (tid == 0) nz = 0;
        __syncthreads();
        if (ei32[tid * 2 + 1] != 0) atomicAdd(&nz, 1);  // odd words zero => int64
        __syncthreads();
        if (tid == 0) g_is64 = (nz == 0) ? 1 : 0;
        if (tid < NB_SCAN) g_lb[tid] = 0ULL;
        return;
    }
    // bids 1..32: pack W into mma B-fragment layout (8192 float2 entries)
    int e = (bid - 1) * 256 + tid;
    int n = e >> 6, r = e & 63, ks = r >> 2, tg = r & 3;
    float v0 = tf32r(W[(ks * 8 + tg) * HF + n]);
    float v1 = tf32r(W[(ks * 8 + tg + 4) * HF + n]);
    g_Wp[e] = make_float2(v0, v1);
}

// ---------------- shared GEMM tile body (256 thr, 8 warps, 32x32 warp tile) --
// warp: wm = warp>>2 (2 m-groups of 32 rows), head = warp&3 (32 cols)
// B fragments (4 LDG.64/ks) feed BOTH m16 tiles -> 1.5 L1 ops per mma
__device__ __forceinline__ void gemm_tile(
    int blk0, int tid, float* xs, const float* __restrict__ x,
    const float* __restrict__ att_src, const float* __restrict__ att_dst) {
#pragma unroll
    for (int it = 0; it < 8; it++) {
        int fidx = it * 256 + tid;                // float4 index, 2048 total
        int row = fidx >> 5, c4 = (fidx & 31) * 4;
        float4 v = make_float4(0.f, 0.f, 0.f, 0.f);
        if (blk0 + row < NN) v = *(const float4*)(x + (size_t)(blk0 + row) * HF + c4);
        v.x = tf32r(v.x); v.y = tf32r(v.y); v.z = tf32r(v.z); v.w = tf32r(v.w);
        *(float4*)(xs + row * 132 + c4) = v;      // +4 pad: conflict-free frags
    }
    __syncthreads();

    const int warp = tid >> 5, lane = tid & 31;
    const int grp = lane >> 2, tig = lane & 3;
    const int wm = warp >> 2, head = warp & 3;
    const int n0 = head * 32;
    const int rA = wm * 32 + grp;

    const float* p0  = xs + rA * 132;
    const float* p8  = p0 + 8 * 132;
    const float* p16 = p0 + 16 * 132;
    const float* p24 = p0 + 24 * 132;

    float c0[4][4], c1[4][4];
#pragma unroll
    for (int j = 0; j < 4; j++)
#pragma unroll
        for (int q = 0; q < 4; q++) { c0[j][q] = 0.f; c1[j][q] = 0.f; }

#pragma unroll
    for (int ks = 0; ks < 16; ks++) {
        int k0 = ks * 8;
        unsigned a00 = __float_as_uint(p0[k0 + tig]);
        unsigned a01 = __float_as_uint(p8[k0 + tig]);
        unsigned a02 = __float_as_uint(p0[k0 + tig + 4]);
        unsigned a03 = __float_as_uint(p8[k0 + tig + 4]);
        unsigned a10 = __float_as_uint(p16[k0 + tig]);
        unsigned a11 = __float_as_uint(p24[k0 + tig]);
        unsigned a12 = __float_as_uint(p16[k0 + tig + 4]);
        unsigned a13 = __float_as_uint(p24[k0 + tig + 4]);
#pragma unroll
        for (int j = 0; j < 4; j++) {
            int n = n0 + j * 8 + grp;
            float2 b = g_Wp[(n * 16 + ks) * 4 + tig];
            unsigned b0 = __float_as_uint(b.x), b1 = __float_as_uint(b.y);
            asm("mma.sync.aligned.m16n8k8.row.col.f32.tf32.tf32.f32 "
                "{%0,%1,%2,%3}, {%4,%5,%6,%7}, {%8,%9}, {%0,%1,%2,%3};"
                : "+f"(c0[j][0]), "+f"(c0[j][1]), "+f"(c0[j][2]), "+f"(c0[j][3])
                : "r"(a00), "r"(a01), "r"(a02), "r"(a03), "r"(b0), "r"(b1));
            asm("mma.sync.aligned.m16n8k8.row.col.f32.tf32.tf32.f32 "
                "{%0,%1,%2,%3}, {%4,%5,%6,%7}, {%8,%9}, {%0,%1,%2,%3};"
                : "+f"(c1[j][0]), "+f"(c1[j][1]), "+f"(c1[j][2]), "+f"(c1[j][3])
                : "r"(a10), "r"(a11), "r"(a12), "r"(a13), "r"(b0), "r"(b1));
        }
    }

    // epilogue: 4 rows per thread-quad: rA, rA+8, rA+16, rA+24
#pragma unroll
    for (int rt = 0; rt < 4; rt++) {
        int row = blk0 + rA + rt * 8;
        float2 v[4];
#pragma unroll
        for (int j = 0; j < 4; j++) {
            float lo = (rt == 0) ? c0[j][0] : (rt == 1) ? c0[j][2] : (rt == 2) ? c1[j][0] : c1[j][2];
            float hi = (rt == 0) ? c0[j][1] : (rt == 1) ? c0[j][3] : (rt == 2) ? c1[j][1] : c1[j][3];
            v[j] = make_float2(lo, hi);
        }
        float ps = 0.f, pd = 0.f;
#pragma unroll
        for (int j = 0; j < 4; j++) {
            int col = j * 8 + tig * 2;
            ps += v[j].x * att_src[n0 + col] + v[j].y * att_src[n0 + col + 1];
            pd += v[j].x * att_dst[n0 + col] + v[j].y * att_dst[n0 + col + 1];
        }
#pragma unroll
        for (int o = 1; o < 4; o <<= 1) {  // quad reduce (unconditional: no divergence)
            ps += __shfl_xor_sync(0xFFFFFFFFu, ps, o);
            pd += __shfl_xor_sync(0xFFFFFFFFu, pd, o);
        }
        if (row < NN) {
            if (tig == 0) { g_asrc[row * 4 + head] = ps; g_adst[row * 4 + head] = pd; }
#pragma unroll
            for (int j = 0; j < 4; j++) {
                half2 hp = __floats2half2_rn(v[j].x, v[j].y);
                g_hh[(size_t)row * 64 + (n0 + j * 8 + tig * 2) / 2] = *(unsigned int*)&hp;
            }
        }
    }
}

// ---------------- kernel 2: gemm part A || degree count ----------------------
__global__ __launch_bounds__(256) void gemm_count_kernel(
    const float* __restrict__ x,
    const float* __restrict__ att_src, const float* __restrict__ att_dst,
    const void* __restrict__ eiv) {
    __shared__ float xs[BM * 132];
    if (blockIdx.x < NG1) { gemm_tile(blockIdx.x * BM, threadIdx.x, xs, x, att_src, att_dst); return; }
    int t = (blockIdx.x - NG1) * 256 + threadIdx.x;
    if (t < EE) {
        int dst;
        if (g_is64) dst = (int)((const long long*)eiv)[EE + t];
        else        dst = ((const int*)eiv)[EE + t];
        atomicAdd(&g_deg[dst], 1);
    }
}

// ---------------- kernel 3: single-kernel scan (decoupled lookback) ----------
__global__ __launch_bounds__(1024) void scan_fused_kernel() {
    __shared__ int sm[1024];
    __shared__ int s_off;
    const int bid = blockIdx.x, tid = threadIdx.x;
    const int i = bid * 1024 + tid;
    int v = 0;
    if (i < NN) { v = g_deg[i] + 1; g_deg[i] = 0; }  // +1 self loop; reset for replay
    sm[tid] = v;
    __syncthreads();
    for (int o = 1; o < 1024; o <<= 1) {
        int t = (tid >= (unsigned)o) ? sm[tid - o] : 0;
        __syncthreads();
        sm[tid] += t;
        __syncthreads();
    }
    int incl = sm[tid];

    if (tid == 1023)
        atomicExch(&g_lb[bid], (1ULL << 32) | (unsigned long long)(unsigned)incl);

    if (tid < 32) {
        int sum = 0;
        for (int j = tid; j < bid; j += 32) {
            unsigned long long p;
            do { p = *((volatile unsigned long long*)&g_lb[j]); } while (!(p >> 32));
            sum += (int)(unsigned)p;
        }
#pragma unroll
        for (int o = 16; o > 0; o >>= 1) sum += __shfl_xor_sync(0xFFFFFFFFu, sum, o);
        if (tid == 0) s_off = sum;
    }
    __syncthreads();

    if (i < NN) {
        int rs = s_off + incl - v;
        g_rowstart[i] = rs;
        g_cursor[i]   = rs;
    }
    if (bid == NB_SCAN - 1 && tid == 1023) g_rowstart[NN] = EE + NN;
}

// ---------------- kernel 4: gemm part B || CSR scatter ------------------------
__global__ __launch_bounds__(256) void gemm_scatter_kernel(
    const float* __restrict__ x,
    const float* __restrict__ att_src, const float* __restrict__ att_dst,
    const void* __restrict__ eiv) {
    __shared__ float xs[BM * 132];
    if (blockIdx.x < NG2) { gemm_tile((NG1 + blockIdx.x) * BM, threadIdx.x, xs, x, att_src, att_dst); return; }
    int t = (blockIdx.x - NG2) * 256 + threadIdx.x;
    if (t >= EE + NN) return;
    int s, d;
    if (t < EE) {
        if (g_is64) {
            s = (int)((const long long*)eiv)[t];
            d = (int)((const long long*)eiv)[EE + t];
        } else {
            s = ((const int*)eiv)[t];
            d = ((const int*)eiv)[EE + t];
        }
    } else {
        s = d = t - EE;  // self loop
    }
    int p = atomicAdd(&g_cursor[d], 1);
    g_srcs[p] = s;
}

// ---------------- kernel 5: softmax + aggregation, 2 nodes per warp ----------
__global__ __launch_bounds__(256) void aggregate_kernel(
    const float* __restrict__ bias, float* __restrict__ out) {
    const int grp = threadIdx.x >> 4;
    const int l   = threadIdx.x & 15;
    const int i = blockIdx.x * 16 + grp;
    if (i >= NN) return;

    const int head = l >> 2;
    const float adst = g_adst[i * 4 + head];
    const int start = g_rowstart[i];
    const int end   = g_rowstart[i + 1];

    float acc[8];
#pragma unroll
    for (int q = 0; q < 8; q++) acc[q] = 0.f;
    float ssum = 0.f;

    int src_next = g_srcs[start];
    for (int j = start; j < end; j++) {
        int src = src_next;
        if (j + 1 < end) src_next = g_srcs[j + 1];
        float e = g_asrc[src * 4 + head] + adst;
        e = (e > 0.f) ? e : 0.2f * e;
        float w = __expf(e);
        uint4 hp = *(const uint4*)(g_hh + (size_t)src * 64 + l * 4);  // 8 halves
        float2 f0 = __half22float2(*(const half2*)&hp.x);
        float2 f1 = __half22float2(*(const half2*)&hp.y);
        float2 f2 = __half22float2(*(const half2*)&hp.z);
        float2 f3 = __half22float2(*(const half2*)&hp.w);
        ssum += w;
        acc[0] += w * f0.x; acc[1] += w * f0.y;
        acc[2] += w * f1.x; acc[3] += w * f1.y;
        acc[4] += w * f2.x; acc[5] += w * f2.y;
        acc[6] += w * f3.x; acc[7] += w * f3.y;
    }

    float inv = 1.f / ssum;
    float4 b0 = *(const float4*)(bias + l * 8);
    float4 b1 = *(const float4*)(bias + l * 8 + 4);
    float4 o0, o1;
    o0.x = acc[0] * inv + b0.x; o0.y = acc[1] * inv + b0.y;
    o0.z = acc[2] * inv + b0.z; o0.w = acc[3] * inv + b0.w;
    o1.x = acc[4] * inv + b1.x; o1.y = acc[5] * inv + b1.y;
    o1.z = acc[6] * inv + b1.z; o1.w = acc[7] * inv + b1.w;
    *(float4*)(out + (size_t)i * HF + l * 8)     = o0;
    *(float4*)(out + (size_t)i * HF + l * 8 + 4) = o1;
}

// ---------------- launch ----------------
extern "C" void kernel_launch(void* const* d_in, const int* in_sizes, int n_in,
                              void* d_out, int out_size) {
    const float* x    = (const float*)d_in[0];
    const void*  ei   = d_in[1];
    const float* W    = (const float*)d_in[2];
    const float* asv  = (const float*)d_in[3];
    const float* adv  = (const float*)d_in[4];
    const float* bias = (const float*)d_in[5];
    float* out = (float*)d_out;

    detect_pack_kernel<<<33, 256>>>((const int*)ei, W);
    gemm_count_kernel<<<NG1 + NCOUNT, 256>>>(x, asv, adv, ei);
    scan_fused_kernel<<<NB_SCAN, 1024>>>();
    gemm_scatter_kernel<<<NG2 + NSCAT, 256>>>(x, asv, adv, ei);
    aggregate_kernel<<<(NN + 15) / 16, 256>>>(bias, out);
}

// round 14
// speedup vs baseline: 1.6107x; 1.0502x over previous
#include <cuda_runtime.h>
#include <cuda_fp16.h>
#include <cstdint>

#define NN 100000
#define EE 1600000
#define HF 128           // HEADS * OUT_F
#define NB_SCAN 98       // ceil(NN/1024)
#define BM 64            // rows per gemm block
#define NGEMM 1563       // ceil(NN/64) total gemm blocks
#define NG1 600          // gemm blocks overlapped with count
#define NG2 (NGEMM - NG1)
#define NCOUNT 6250      // ceil(EE/256)
#define NSCAT 6641       // ceil((EE+NN)/256)
#define XS_STRIDE 144    // halves per row (128 + 16 pad)

// ---------------- scratch (statics zero-initialized at load) -----------------
__device__ unsigned int g_hh[NN * 64]; // 25.6 MB : h in half2 (64 x uint per row)
__device__ float  g_asrc[NN * 4];
__device__ float  g_adst[NN * 4];
__device__ int    g_deg[NN];           // scan re-zeroes after use (replay-safe)
__device__ int    g_cursor[NN];
__device__ int    g_rowstart[NN + 1];
__device__ int    g_srcs[EE + NN];
__device__ unsigned long long g_lb[NB_SCAN];  // lookback: (flag<<32)|blocksum
__device__ uint2  g_Whp[128 * 8 * 4];  // W in fp16 B-fragment order (32 KB)

// per-block int64 detection: odd int32 words of first 256 int64s all zero => int64
__device__ __forceinline__ int block_is64(const void* eiv) {
    int v = ((const int*)eiv)[(threadIdx.x & 255) * 2 + 1];
    return __syncthreads_or(v != 0) ? 0 : 1;
}

// ---------------- kernel 1: lb clear + W fp16 fragment pack ------------------
__global__ __launch_bounds__(256) void pack_kernel(const float* __restrict__ W) {
    const int bid = blockIdx.x, tid = threadIdx.x;
    if (bid == 0) {
        if (tid < NB_SCAN) g_lb[tid] = 0ULL;
        return;
    }
    int e = (bid - 1) * 256 + tid;       // < 4096 : (n, ks, tig)
    int n = e >> 5, r = e & 31, ks = r >> 2, tg = r & 3;
    int k0 = ks * 16 + tg * 2;
    half2 lo = __floats2half2_rn(W[k0 * HF + n],       W[(k0 + 1) * HF + n]);
    half2 hi = __floats2half2_rn(W[(k0 + 8) * HF + n], W[(k0 + 9) * HF + n]);
    g_Whp[e] = make_uint2(*(unsigned int*)&lo, *(unsigned int*)&hi);
}

// ---------------- GEMM tile body: fp16 mma m16n8k16, 256 thr, 8 warps --------
// warp tile 32x32: wm = warp>>2 (m half), head = warp&3 (32 cols)
// smem layout: per row 128 halves permuted so LDS.64 yields (a0,a2) fragment
// pairs; 4-slot XOR swizzle (slot ^= row&3) -> 2-way-floor bank access
__device__ __forceinline__ void gemm_tile(
    int blk0, int tid, half* xs, const float* __restrict__ x,
    const float* __restrict__ att_src, const float* __restrict__ att_dst) {
#pragma unroll
    for (int it = 0; it < 8; it++) {
        int fidx = it * 256 + tid;            // float4 index, 2048 total
        int row = fidx >> 5, c4 = (fidx & 31) * 4;
        float4 v = make_float4(0.f, 0.f, 0.f, 0.f);
        if (blk0 + row < NN) v = *(const float4*)(x + (size_t)(blk0 + row) * HF + c4);
        int base = c4 & ~15;
        int q  = (c4 >> 1) & 3;               // logical slot of (k, k+1)
        int h2 = (c4 >> 3) & 1;               // within-slot offset (k vs k+8 group)
        int sw = row & 3;
        half* rp = xs + row * XS_STRIDE + base;
        *(half2*)(rp + (q ^ sw) * 4 + h2 * 2)       = __floats2half2_rn(v.x, v.y);
        *(half2*)(rp + ((q + 1) ^ sw) * 4 + h2 * 2) = __floats2half2_rn(v.z, v.w);
    }
    __syncthreads();

    const int warp = tid >> 5, lane = tid & 31;
    const int grp = lane >> 2, tig = lane & 3;
    const int wm = warp >> 2, head = warp & 3;
    const int n0 = head * 32;
    const int rA = wm * 32 + grp;
    const int soff = (tig ^ (grp & 3)) * 4;   // physical slot of logical chunk tig

    const half* p0  = xs + rA * XS_STRIDE;
    const half* p8  = p0 + 8 * XS_STRIDE;
    const half* p16 = p0 + 16 * XS_STRIDE;
    const half* p24 = p0 + 24 * XS_STRIDE;

    float c0[4][4], c1[4][4];
#pragma unroll
    for (int j = 0; j < 4; j++)
#pragma unroll
        for (int q = 0; q < 4; q++) { c0[j][q] = 0.f; c1[j][q] = 0.f; }

#pragma unroll
    for (int ks = 0; ks < 8; ks++) {
        int o = ks * 16 + soff;
        uint2 A0 = *(const uint2*)(p0 + o);   // .x = (rA,   k 2t:2t+1)  .y = (rA,   k 2t+8:+9)
        uint2 A1 = *(const uint2*)(p8 + o);
        uint2 A2 = *(const uint2*)(p16 + o);
        uint2 A3 = *(const uint2*)(p24 + o);
#pragma unroll
        for (int j = 0; j < 4; j++) {
            int n = n0 + j * 8 + grp;
            uint2 b = g_Whp[n * 32 + ks * 4 + tig];
            asm("mma.sync.aligned.m16n8k16.row.col.f32.f16.f16.f32 "
                "{%0,%1,%2,%3}, {%4,%5,%6,%7}, {%8,%9}, {%0,%1,%2,%3};"
                : "+f"(c0[j][0]), "+f"(c0[j][1]), "+f"(c0[j][2]), "+f"(c0[j][3])
                : "r"(A0.x), "r"(A1.x), "r"(A0.y), "r"(A1.y), "r"(b.x), "r"(b.y));
            asm("mma.sync.aligned.m16n8k16.row.col.f32.f16.f16.f32 "
                "{%0,%1,%2,%3}, {%4,%5,%6,%7}, {%8,%9}, {%0,%1,%2,%3};"
                : "+f"(c1[j][0]), "+f"(c1[j][1]), "+f"(c1[j][2]), "+f"(c1[j][3])
                : "r"(A2.x), "r"(A3.x), "r"(A2.y), "r"(A3.y), "r"(b.x), "r"(b.y));
        }
    }

    // epilogue: 4 rows per thread-quad: rA, rA+8, rA+16, rA+24
#pragma unroll
    for (int rt = 0; rt < 4; rt++) {
        int row = blk0 + rA + rt * 8;
        float2 v[4];
#pragma unroll
        for (int j = 0; j < 4; j++) {
            float lo = (rt == 0) ? c0[j][0] : (rt == 1) ? c0[j][2] : (rt == 2) ? c1[j][0] : c1[j][2];
            float hi = (rt == 0) ? c0[j][1] : (rt == 1) ? c0[j][3] : (rt == 2) ? c1[j][1] : c1[j][3];
            v[j] = make_float2(lo, hi);
        }
        float ps = 0.f, pd = 0.f;
#pragma unroll
        for (int j = 0; j < 4; j++) {
            int col = j * 8 + tig * 2;
            ps += v[j].x * att_src[n0 + col] + v[j].y * att_src[n0 + col + 1];
            pd += v[j].x * att_dst[n0 + col] + v[j].y * att_dst[n0 + col + 1];
        }
#pragma unroll
        for (int o = 1; o < 4; o <<= 1) {
            ps += __shfl_xor_sync(0xFFFFFFFFu, ps, o);
            pd += __shfl_xor_sync(0xFFFFFFFFu, pd, o);
        }
        if (row < NN) {
            if (tig == 0) { g_asrc[row * 4 + head] = ps; g_adst[row * 4 + head] = pd; }
#pragma unroll
            for (int j = 0; j < 4; j++) {
                half2 hp = __floats2half2_rn(v[j].x, v[j].y);
                g_hh[(size_t)row * 64 + (n0 + j * 8 + tig * 2) / 2] = *(unsigned int*)&hp;
            }
        }
    }
}

// ---------------- kernel 2: gemm part A || degree count ----------------------
__global__ __launch_bounds__(256) void gemm_count_kernel(
    const float* __restrict__ x,
    const float* __restrict__ att_src, const float* __restrict__ att_dst,
    const void* __restrict__ eiv) {
    __shared__ __align__(16) half xs[BM * XS_STRIDE];
    if (blockIdx.x < NG1) { gemm_tile(blockIdx.x * BM, threadIdx.x, xs, x, att_src, att_dst); return; }
    int is64 = block_is64(eiv);
    int t = (blockIdx.x - NG1) * 256 + threadIdx.x;
    if (t < EE) {
        int dst;
        if (is64) dst = (int)((const long long*)eiv)[EE + t];
        else      dst = ((const int*)eiv)[EE + t];
        atomicAdd(&g_deg[dst], 1);
    }
}

// ---------------- kernel 3: single-kernel scan (decoupled lookback) ----------
__global__ __launch_bounds__(1024) void scan_fused_kernel() {
    __shared__ int sm[1024];
    __shared__ int s_off;
    const int bid = blockIdx.x, tid = threadIdx.x;
    const int i = bid * 1024 + tid;
    int v = 0;
    if (i < NN) { v = g_deg[i] + 1; g_deg[i] = 0; }  // +1 self loop; reset for replay
    sm[tid] = v;
    __syncthreads();
    for (int o = 1; o < 1024; o <<= 1) {
        int t = (tid >= (unsigned)o) ? sm[tid - o] : 0;
        __syncthreads();
        sm[tid] += t;
        __syncthreads();
    }
    int incl = sm[tid];

    if (tid == 1023)
        atomicExch(&g_lb[bid], (1ULL << 32) | (unsigned long long)(unsigned)incl);

    if (tid < 32) {
        int sum = 0;
        for (int j = tid; j < bid; j += 32) {
            unsigned long long p;
            do { p = *((volatile unsigned long long*)&g_lb[j]); } while (!(p >> 32));
            sum += (int)(unsigned)p;
        }
#pragma unroll
        for (int o = 16; o > 0; o >>= 1) sum += __shfl_xor_sync(0xFFFFFFFFu, sum, o);
        if (tid == 0) s_off = sum;
    }
    __syncthreads();

    if (i < NN) {
        int rs = s_off + incl - v;
        g_rowstart[i] = rs;
        g_cursor[i]   = rs;
    }
    if (bid == NB_SCAN - 1 && tid == 1023) g_rowstart[NN] = EE + NN;
}

// ---------------- kernel 4: gemm part B || CSR scatter ------------------------
__global__ __launch_bounds__(256) void gemm_scatter_kernel(
    const float* __restrict__ x,
    const float* __restrict__ att_src, const float* __restrict__ att_dst,
    const void* __restrict__ eiv) {
    __shared__ __align__(16) half xs[BM * XS_STRIDE];
    if (blockIdx.x < NG2) { gemm_tile((NG1 + blockIdx.x) * BM, threadIdx.x, xs, x, att_src, att_dst); return; }
    int is64 = block_is64(eiv);
    int t = (blockIdx.x - NG2) * 256 + threadIdx.x;
    if (t >= EE + NN) return;
    int s, d;
    if (t < EE) {
        if (is64) {
            s = (int)((const long long*)eiv)[t];
            d = (int)((const long long*)eiv)[EE + t];
        } else {
            s = ((const int*)eiv)[t];
            d = ((const int*)eiv)[EE + t];
        }
    } else {
        s = d = t - EE;  // self loop
    }
    int p = atomicAdd(&g_cursor[d], 1);
    g_srcs[p] = s;
}

// ---------------- kernel 5: softmax + aggregation, 2 nodes per warp ----------
__global__ __launch_bounds__(256) void aggregate_kernel(
    const float* __restrict__ bias, float* __restrict__ out) {
    const int grp = threadIdx.x >> 4;
    const int l   = threadIdx.x & 15;
    const int i = blockIdx.x * 16 + grp;
    if (i >= NN) return;

    const int head = l >> 2;
    const float adst = g_adst[i * 4 + head];
    const int start = g_rowstart[i];
    const int end   = g_rowstart[i + 1];

    float acc[8];
#pragma unroll
    for (int q = 0; q < 8; q++) acc[q] = 0.f;
    float ssum = 0.f;

    int src_next = g_srcs[start];
    for (int j = start; j < end; j++) {
        int src = src_next;
        if (j + 1 < end) src_next = g_srcs[j + 1];
        float e = g_asrc[src * 4 + head] + adst;
        e = (e > 0.f) ? e : 0.2f * e;
        float w = __expf(e);
        uint4 hp = *(const uint4*)(g_hh + (size_t)src * 64 + l * 4);  // 8 halves
        float2 f0 = __half22float2(*(const half2*)&hp.x);
        float2 f1 = __half22float2(*(const half2*)&hp.y);
        float2 f2 = __half22float2(*(const half2*)&hp.z);
        float2 f3 = __half22float2(*(const half2*)&hp.w);
        ssum += w;
        acc[0] += w * f0.x; acc[1] += w * f0.y;
        acc[2] += w * f1.x; acc[3] += w * f1.y;
        acc[4] += w * f2.x; acc[5] += w * f2.y;
        acc[6] += w * f3.x; acc[7] += w * f3.y;
    }

    float inv = 1.f / ssum;
    float4 b0 = *(const float4*)(bias + l * 8);
    float4 b1 = *(const float4*)(bias + l * 8 + 4);
    float4 o0, o1;
    o0.x = acc[0] * inv + b0.x; o0.y = acc[1] * inv + b0.y;
    o0.z = acc[2] * inv + b0.z; o0.w = acc[3] * inv + b0.w;
    o1.x = acc[4] * inv + b1.x; o1.y = acc[5] * inv + b1.y;
    o1.z = acc[6] * inv + b1.z; o1.w = acc[7] * inv + b1.w;
    *(float4*)(out + (size_t)i * HF + l * 8)     = o0;
    *(float4*)(out + (size_t)i * HF + l * 8 + 4) = o1;
}

// ---------------- launch ----------------
extern "C" void kernel_launch(void* const* d_in, const int* in_sizes, int n_in,
                              void* d_out, int out_size) {
    const float* x    = (const float*)d_in[0];
    const void*  ei   = d_in[1];
    const float* W    = (const float*)d_in[2];
    const float* asv  = (const float*)d_in[3];
    const float* adv  = (const float*)d_in[4];
    const float* bias = (const float*)d_in[5];
    float* out = (float*)d_out;

    pack_kernel<<<17, 256>>>(W);
    gemm_count_kernel<<<NG1 + NCOUNT, 256>>>(x, asv, adv, ei);
    scan_fused_kernel<<<NB_SCAN, 1024>>>();
    gemm_scatter_kernel<<<NG2 + NSCAT, 256>>>(x, asv, adv, ei);
    aggregate_kernel<<<(NN + 15) / 16, 256>>>(bias, out);
}